// round 7
// baseline (speedup 1.0000x reference)
#include <cuda_runtime.h>

#define SAMPLES 16
#define THREADS 256

#define SIN_STR 324    // staged input per-sample stride: 16 rows x 20 cols (+4 pad)
#define C1STR   808    // conv1-out per-sample stride: [y][8 xx][12 ch] rows of 100 (+8 pad)
#define O2STR   17     // conv2-out transposed: [192 k][17]

enum {
    OFF_C1   = 0,                          // 16 * 808 = 12928
    OFF_R2   = 16 * C1STR,                 // 12928: input stage (16*324=5184), later out2t
    OFF_HID  = OFF_R2 + 192 * O2STR,       // 16192 (+512 = 16704 <= 18112, inside stage)
    OFF_W1T  = OFF_R2 + 16 * SIN_STR,      // 18112: w1 [25 tap][12 ch]
    OFF_B1T  = OFF_W1T + 304,              // 18416: b1 pairs [6 j][8 xx][8 y][2]
    OFF_W2T  = OFF_B1T + 768,              // 19184: w2 [25 tap][12 o][8 j]
    OFF_H2B  = OFF_W2T + 2400,             // 21584: [12][16]
    OFF_W3T  = OFF_H2B + 192,              // 21776: w3 [30 h][192 k]
    OFF_H3B  = OFF_W3T + 5760,             // 27536
    OFF_OUTW = OFF_H3B + 32,               // 27568: [30][10]
    OFF_OUTB = OFF_OUTW + 304,             // 27872
    OFF_NEG  = OFF_OUTB + 16,              // 27888: 20 floats of -1 (shared pad row)
    SMEM_FLOATS = OFF_NEG + 20             // 27908 floats = 111632 B -> 2 blocks/SM
};

typedef unsigned long long ull;

__device__ __forceinline__ ull pk2(float a, float b) {
    ull r; asm("mov.b64 %0, {%1, %2};" : "=l"(r) : "f"(a), "f"(b)); return r;
}
__device__ __forceinline__ void fma2(ull& d, ull a, ull b) {
    asm("fma.rn.f32x2 %0, %1, %2, %0;" : "+l"(d) : "l"(a), "l"(b));
}
__device__ __forceinline__ void unpk2(ull v, float& lo, float& hi) {
    asm("mov.b64 {%0, %1}, %2;" : "=f"(lo), "=f"(hi) : "l"(v));
}

__global__ void __launch_bounds__(THREADS, 2)
modernnet_fused_kernel(const float* __restrict__ x,
                       const float* __restrict__ w1,   // [12,1,5,5]
                       const float* __restrict__ b1,   // [12,8,8]
                       const float* __restrict__ w2,   // [12,8,5,5]
                       const float* __restrict__ b2,   // [12,4,4]
                       const float* __restrict__ w3,   // [192,30]
                       const float* __restrict__ b3,   // [30]
                       const float* __restrict__ wo,   // [30,10]
                       const float* __restrict__ bo,   // [10]
                       float* __restrict__ out,        // [B,10]
                       int nsamp)
{
    extern __shared__ float sm[];
    const int t = threadIdx.x;
    const long base_s = (long)blockIdx.x * SAMPLES;

    // ---------------- Phase A: stage input (with -1 halo) + weights ----------
    for (int i = t; i < SAMPLES * 320; i += THREADS) {
        int s = i / 320, rem = i - s * 320;
        int r = rem / 20, c20 = rem - r * 20;
        int cc = c20 - 2;                       // halo cols -2..17
        long gs = base_s + s;
        float v = -1.0f;
        if ((unsigned)cc < 16u && gs < nsamp) v = x[gs * 256 + r * 16 + cc];
        sm[OFF_R2 + s * SIN_STR + r * 20 + c20] = v;
    }
    // w1t[k*12 + c] = w1[c*25 + k]
    for (int i = t; i < 300; i += THREADS) {
        int c = i / 25, k = i - c * 25;
        sm[OFF_W1T + k * 12 + c] = w1[i];
    }
    // b1 packed pairs: b1t[((j*8+xx)*8 + y)*2 + lh] = b1[(2j+lh)*64 + y*8+xx]
    for (int i = t; i < 768; i += THREADS) {
        int i2 = i >> 1, lh = i & 1;
        int j = i2 >> 6, rem = i2 & 63, xx = rem >> 3, y = rem & 7;
        sm[OFF_B1T + i] = b1[(2 * j + lh) * 64 + y * 8 + xx];
    }
    // w2t[k*96 + o*8 + j] = w2[o*200 + j*25 + k]  (j = o's 8 inputs, ascending c)
    for (int i = t; i < 2400; i += THREADS) {
        int k = i / 96, rem = i - k * 96, o = rem >> 3, j = rem & 7;
        sm[OFF_W2T + i] = w2[o * 200 + j * 25 + k];
    }
    for (int i = t; i < 192; i += THREADS) sm[OFF_H2B + i] = b2[i];
    // w3t[h*192 + k] = w3[k*30 + h]
    for (int i = t; i < 5760; i += THREADS) {
        int k = i / 30, h = i - k * 30;
        sm[OFF_W3T + h * 192 + k] = w3[i];
    }
    for (int i = t; i < 30;  i += THREADS) sm[OFF_H3B + i]  = b3[i];
    for (int i = t; i < 300; i += THREADS) sm[OFF_OUTW + i] = wo[i];
    for (int i = t; i < 10;  i += THREADS) sm[OFF_OUTB + i] = bo[i];
    if (t < 20) sm[OFF_NEG + t] = -1.0f;
    __syncthreads();

    // -------- Phase B: conv1, thread = (sample, row, x-half), 4 cols ---------
    {
        int s = t >> 4, sub = t & 15;
        int y = sub & 7, xh = sub >> 3;             // xh = 0/1 -> xx in [4*xh, 4*xh+4)
        const float* sin_ = &sm[OFF_R2 + s * SIN_STR];
        const float* negrow = &sm[OFF_NEG];

        ull A[24];                                  // [lx][6 ch-pairs]
#pragma unroll
        for (int lx = 0; lx < 4; lx++)
#pragma unroll
            for (int j = 0; j < 6; j++)
                A[lx * 6 + j] =
                    *(const ull*)&sm[OFF_B1T + ((j * 8 + (xh * 4 + lx)) * 8 + y) * 2];

        for (int ky = 0; ky < 5; ky++) {
            int r = 2 * y + ky - 2;
            const float* rowbase = ((unsigned)r < 16u) ? (sin_ + r * 20) : negrow;
            const float4* rowp = (const float4*)(rowbase + xh * 8);  // 12 floats
            float v[12];
            float4 m0 = rowp[0], m1 = rowp[1], m2 = rowp[2];
            v[0]=m0.x; v[1]=m0.y; v[2]=m0.z; v[3]=m0.w;
            v[4]=m1.x; v[5]=m1.y; v[6]=m1.z; v[7]=m1.w;
            v[8]=m2.x; v[9]=m2.y; v[10]=m2.z; v[11]=m2.w;
#pragma unroll
            for (int kx = 0; kx < 5; kx++) {
                const ulonglong2* wp =
                    (const ulonglong2*)&sm[OFF_W1T + (ky * 5 + kx) * 12];
                ulonglong2 p0 = wp[0], p1 = wp[1], p2 = wp[2];
#pragma unroll
                for (int lx = 0; lx < 4; lx++) {
                    float vs = v[2 * lx + kx];
                    ull vv = pk2(vs, vs);
                    fma2(A[lx*6+0], vv, p0.x); fma2(A[lx*6+1], vv, p0.y);
                    fma2(A[lx*6+2], vv, p1.x); fma2(A[lx*6+3], vv, p1.y);
                    fma2(A[lx*6+4], vv, p2.x); fma2(A[lx*6+5], vv, p2.y);
                }
            }
        }
        // relu + store channel-minor [y][xx][12], 3x STS.128 per column
        float* c1s = &sm[OFF_C1 + s * C1STR];
#pragma unroll
        for (int lx = 0; lx < 4; lx++) {
            int xx = xh * 4 + lx;
            float f[12];
#pragma unroll
            for (int j = 0; j < 6; j++) unpk2(A[lx * 6 + j], f[2 * j], f[2 * j + 1]);
#pragma unroll
            for (int c = 0; c < 12; c++) f[c] = f[c] > 0.0f ? f[c] : 0.0f;
            float4* dst = (float4*)&c1s[y * 100 + xx * 12];
            dst[0] = make_float4(f[0], f[1], f[2],  f[3]);
            dst[1] = make_float4(f[4], f[5], f[6],  f[7]);
            dst[2] = make_float4(f[8], f[9], f[10], f[11]);
        }
    }
    __syncthreads();

    // ---------------- Phase C: conv2, thread = (sample, pos) -----------------
    {
        int s = t >> 4, pos = t & 15;
        int ii = pos >> 2, jj = pos & 3;
        const float* c1a = &sm[OFF_C1 + s * C1STR];
        const float* negrow = &sm[OFF_NEG];

        ull acA[12];
#pragma unroll
        for (int o = 0; o < 12; o++) acA[o] = 0;

        for (int ky = 0; ky < 5; ky++) {
            int yy = 2 * ii + ky - 2;
            for (int kx = 0; kx < 5; kx++) {
                int xx2 = 2 * jj + kx - 2;
                bool ok = ((unsigned)yy < 8u) && ((unsigned)xx2 < 8u);
                int ad = yy * 100 + xx2 * 12;
                const ulonglong2* pa = (const ulonglong2*)(ok ? (c1a + ad) : negrow);
                ulonglong2 qa0 = pa[0], qa1 = pa[1], qa2 = pa[2];
                ull a0[6] = {qa0.x, qa0.y, qa1.x, qa1.y, qa2.x, qa2.y};
                int k = ky * 5 + kx;
#pragma unroll
                for (int o = 0; o < 12; o++) {
                    const int p0 = (o < 8) ? ((o < 4) ? 0 : 2) : 0;
                    const int p1 = (o < 4) ? 2 : 4;
                    const ulonglong2* wp =
                        (const ulonglong2*)&sm[OFF_W2T + k * 96 + o * 8];
                    ulonglong2 wA = wp[0], wB = wp[1];
                    fma2(acA[o], a0[p0],     wA.x);
                    fma2(acA[o], a0[p0 + 1], wA.y);
                    fma2(acA[o], a0[p1],     wB.x);
                    fma2(acA[o], a0[p1 + 1], wB.y);
                }
            }
        }
        // bias + relu + transposed store out2t[k][17 + s]
        float* o2 = &sm[OFF_R2];
#pragma unroll
        for (int o = 0; o < 12; o++) {
            float lo, hi, bias = sm[OFF_H2B + o * 16 + pos];
            unpk2(acA[o], lo, hi);
            float va = lo + hi + bias;
            o2[(o * 16 + pos) * O2STR + s] = va > 0.0f ? va : 0.0f;
        }
    }
    __syncthreads();

    // ---------------- Phase D: fc1 192->30 + relu (1 sample, 2 h / thread) ---
    if (t < 240) {
        int h2 = t >> 4, s = t & 15;
        int h0 = 2 * h2, h1 = 2 * h2 + 1;
        const float* o2 = &sm[OFF_R2];
        const ulonglong2* wp0 = (const ulonglong2*)&sm[OFF_W3T + h0 * 192];
        const ulonglong2* wp1 = (const ulonglong2*)&sm[OFF_W3T + h1 * 192];
        ull s0p = 0, s1p = 0;
#pragma unroll 8
        for (int k4 = 0; k4 < 48; k4++) {
            ulonglong2 wa = wp0[k4], wb = wp1[k4];
            int k = 4 * k4;
            float a0 = o2[(k+0)*O2STR + s], a1 = o2[(k+1)*O2STR + s];
            float a2 = o2[(k+2)*O2STR + s], a3 = o2[(k+3)*O2STR + s];
            ull va01 = pk2(a0, a1), va23 = pk2(a2, a3);
            fma2(s0p, va01, wa.x); fma2(s0p, va23, wa.y);
            fma2(s1p, va01, wb.x); fma2(s1p, va23, wb.y);
        }
        float lo, hi;
        unpk2(s0p, lo, hi); float v0 = lo + hi + sm[OFF_H3B + h0];
        unpk2(s1p, lo, hi); float v1 = lo + hi + sm[OFF_H3B + h1];
        sm[OFF_HID + s * 32 + h0] = v0 > 0.0f ? v0 : 0.0f;
        sm[OFF_HID + s * 32 + h1] = v1 > 0.0f ? v1 : 0.0f;
    }
    __syncthreads();

    // ---------------- Phase E: fc2 30->10, write output ----------------------
    if (t < 160) {
        int s = t / 10, o = t - s * 10;
        float sum = sm[OFF_OUTB + o];
        const float* hid = &sm[OFF_HID + s * 32];
#pragma unroll
        for (int h = 0; h < 30; h++)
            sum += hid[h] * sm[OFF_OUTW + h * 10 + o];
        long gs = base_s + s;
        if (gs < nsamp) out[gs * 10 + o] = sum;
    }
}

extern "C" void kernel_launch(void* const* d_in, const int* in_sizes, int n_in,
                              void* d_out, int out_size)
{
    const float* x  = (const float*)d_in[0];
    const float* w1 = (const float*)d_in[1];
    const float* b1 = (const float*)d_in[2];
    const float* w2 = (const float*)d_in[3];
    const float* b2 = (const float*)d_in[4];
    const float* w3 = (const float*)d_in[5];
    const float* b3 = (const float*)d_in[6];
    const float* wo = (const float*)d_in[7];
    const float* bo = (const float*)d_in[8];
    float* out = (float*)d_out;

    int nsamp = in_sizes[0] / 256;                       // 131072
    int grid  = (nsamp + SAMPLES - 1) / SAMPLES;         // 8192
    size_t smem = SMEM_FLOATS * sizeof(float);           // 111632 B

    cudaFuncSetAttribute(modernnet_fused_kernel,
                         cudaFuncAttributeMaxDynamicSharedMemorySize, (int)smem);
    modernnet_fused_kernel<<<grid, THREADS, smem>>>(x, w1, b1, w2, b2, w3, b3,
                                                    wo, bo, out, nsamp);
}